// round 12
// baseline (speedup 1.0000x reference)
#include <cuda_runtime.h>
#include <cstdint>
#include <cstddef>

#define BD 4096   // batch (M)
#define ID 2048   // in features (K)
#define FD 4096   // out features (N)

// ---------------------------------------------------------------------------
// Scratch (device globals; zero-initialized at load; no dynamic allocation)
// ---------------------------------------------------------------------------
__device__ float       g_xbuf[(size_t)BD * ID];
__device__ float       g_wbuf[(size_t)ID * FD];
__device__ float       g_zbuf[(size_t)BD * FD];
__device__ int         g_acc [(size_t)BD * FD];
__device__ signed char g_qx  [(size_t)BD * ID];
__device__ signed char g_qwT [(size_t)FD * ID];
// atomicMax over identical inputs is idempotent -> deterministic across replays
__device__ unsigned    g_maxbits[2];
// GEMM work-stealing counter; reset by quant_xw_kernel block 0 each run
__device__ unsigned    g_tilectr;

// ===========================================================================
// FWHT building blocks
// ===========================================================================
template<typename Tin, bool DO_MAX>
__device__ __forceinline__ void fwht_row_body(const Tin* __restrict__ in,
                                              float* __restrict__ out,
                                              float4* s4, float* red,
                                              int row, float scale,
                                              unsigned* __restrict__ maxbits)
{
    const int t = threadIdx.x;
    const int l = t & 31;
    const int w = t >> 5;

    float v[4];
    {
        const Tin* rp = in + (size_t)row * 4096;
        float4 f;
        if constexpr ((bool)__is_same(Tin, int)) {
            int4 q = ((const int4*)rp)[t];
            f = make_float4((float)q.x, (float)q.y, (float)q.z, (float)q.w);
        } else {
            f = ((const float4*)rp)[t];
        }
        v[0] = f.x; v[1] = f.y; v[2] = f.z; v[3] = f.w;
    }

    { float a, b;
      a = v[0]; b = v[1]; v[0] = a + b; v[1] = a - b;
      a = v[2]; b = v[3]; v[2] = a + b; v[3] = a - b;
      a = v[0]; b = v[2]; v[0] = a + b; v[2] = a - b;
      a = v[1]; b = v[3]; v[1] = a + b; v[3] = a - b; }

    #pragma unroll
    for (int m = 1; m <= 16; m <<= 1) {
        #pragma unroll
        for (int j = 0; j < 4; ++j) {
            float per = __shfl_xor_sync(0xffffffffu, v[j], m);
            v[j] = (l & m) ? per - v[j] : v[j] + per;
        }
    }

    s4[t ^ w] = make_float4(v[0], v[1], v[2], v[3]);
    __syncthreads();
    {
        int r4 = (l << 5) | w;
        float4 f = s4[r4 ^ l];
        v[0] = f.x; v[1] = f.y; v[2] = f.z; v[3] = f.w;
    }

    #pragma unroll
    for (int m = 1; m <= 16; m <<= 1) {
        #pragma unroll
        for (int j = 0; j < 4; ++j) {
            float per = __shfl_xor_sync(0xffffffffu, v[j], m);
            v[j] = (l & m) ? per - v[j] : v[j] + per;
        }
    }

    {
        int r4 = (l << 5) | w;
        s4[r4 ^ l] = make_float4(v[0], v[1], v[2], v[3]);
    }
    __syncthreads();
    float4 f = s4[t ^ w];

    float4 o = make_float4(f.x * scale, f.y * scale, f.z * scale, f.w * scale);
    ((float4*)(out + (size_t)row * 4096))[t] = o;

    if (DO_MAX) {
        float lmax = fmaxf(fmaxf(fabsf(o.x), fabsf(o.y)), fmaxf(fabsf(o.z), fabsf(o.w)));
        #pragma unroll
        for (int m = 16; m; m >>= 1) lmax = fmaxf(lmax, __shfl_xor_sync(0xffffffffu, lmax, m));
        if (l == 0) red[w] = lmax;
        __syncthreads();
        if (t < 32) {
            float r2 = red[t];
            #pragma unroll
            for (int m = 16; m; m >>= 1) r2 = fmaxf(r2, __shfl_xor_sync(0xffffffffu, r2, m));
            if (t == 0) atomicMax(maxbits, __float_as_uint(r2));
        }
    }
}

template<bool DO_MAX, bool FINAL>
__device__ __forceinline__ void fwht_dim0_body(const float* __restrict__ in,
                                               float* __restrict__ out,
                                               float4* sm4, float* red,
                                               int ncols, int c0, float scale,
                                               const unsigned* __restrict__ scalebits,
                                               unsigned* __restrict__ maxbits,
                                               const float* __restrict__ bias)
{
    const int t = threadIdx.x;
    const int c = t & 7;
    const int p = t >> 3;
    const int l = t & 31;
    const int w = t >> 5;

    float v[32];

    {
        const float* ip = in + (size_t)(p << 5) * ncols + c0 + c;
        #pragma unroll
        for (int j = 0; j < 32; ++j) v[j] = ip[(size_t)j * ncols];
    }

    #pragma unroll
    for (int st = 0; st < 5; ++st) {
        const int h = 1 << st;
        #pragma unroll
        for (int j = 0; j < 32; ++j)
            if ((j & h) == 0) {
                float a = v[j], b = v[j + h];
                v[j] = a + b; v[j + h] = a - b;
            }
    }

    #pragma unroll
    for (int m = 8; m <= 16; m <<= 1) {
        #pragma unroll
        for (int j = 0; j < 32; ++j) {
            float per = __shfl_xor_sync(0xffffffffu, v[j], m);
            v[j] = (l & m) ? per - v[j] : v[j] + per;
        }
    }

    #pragma unroll
    for (int jj = 0; jj < 8; ++jj) {
        int phys = (c << 10) + (((p << 3) + jj) ^ c);
        sm4[phys] = make_float4(v[4 * jj], v[4 * jj + 1], v[4 * jj + 2], v[4 * jj + 3]);
    }
    __syncthreads();

    {
        const float* smf = (const float*)sm4;
        #pragma unroll
        for (int j = 0; j < 32; ++j) {
            int q  = (j << 5) + w;
            int phys = (c << 10) + (q ^ c);
            v[j] = smf[phys * 4 + (p & 3)];
        }
    }

    #pragma unroll
    for (int st = 0; st < 5; ++st) {
        const int h = 1 << st;
        #pragma unroll
        for (int j = 0; j < 32; ++j)
            if ((j & h) == 0) {
                float a = v[j], b = v[j + h];
                v[j] = a + b; v[j + h] = a - b;
            }
    }

    float sc = scale;
    float bv = 0.0f;
    if (FINAL) {
        float sx = __uint_as_float(scalebits[0]) / 127.0f;
        float sw = __uint_as_float(scalebits[1]) / 127.0f;
        sc *= sx * sw;
        bv = bias[c0 + c];
    }

    float lmax = 0.0f;
    {
        float* op = out + (size_t)p * ncols + c0 + c;
        #pragma unroll
        for (int j = 0; j < 32; ++j) {
            float o = v[j] * sc + bv;
            op[(size_t)(j << 7) * ncols] = o;
            if (DO_MAX) lmax = fmaxf(lmax, fabsf(o));
        }
    }

    if (DO_MAX) {
        #pragma unroll
        for (int m = 16; m; m >>= 1) lmax = fmaxf(lmax, __shfl_xor_sync(0xffffffffu, lmax, m));
        if (l == 0) red[w] = lmax;
        __syncthreads();
        if (t < 32) {
            float r2 = red[t];
            #pragma unroll
            for (int m = 16; m; m >>= 1) r2 = fmaxf(r2, __shfl_xor_sync(0xffffffffu, r2, m));
            if (t == 0) atomicMax(maxbits, __float_as_uint(r2));
        }
    }
}

__global__ __launch_bounds__(1024)
void fwht_dim0_x_kernel(const float* __restrict__ x, float* __restrict__ xr,
                        unsigned* __restrict__ mx)
{
    extern __shared__ float4 dsm4[];
    __shared__ float red[32];
    fwht_dim0_body<true, false>(x, xr, dsm4, red, ID, blockIdx.x * 8,
                                1.0f / 64.0f, nullptr, mx + 0, nullptr);
}

__global__ __launch_bounds__(1024, 2)
void fwht_rows_w_kernel(const float* __restrict__ w, float* __restrict__ wr,
                        unsigned* __restrict__ mx)
{
    __shared__ float4 s4[1024];
    __shared__ float red[32];
    fwht_row_body<float, true>(w, wr, s4, red, blockIdx.x, 1.0f / 64.0f, mx + 1);
}

__global__ __launch_bounds__(1024, 2)
void fwht_rows_acc_kernel(const int* __restrict__ in, float* __restrict__ out)
{
    __shared__ float4 s4[1024];
    __shared__ float red[32];
    fwht_row_body<int, false>(in, out, s4, red, blockIdx.x, 1.0f, nullptr);
}

__global__ __launch_bounds__(1024)
void fwht_dim0_final_kernel(const float* __restrict__ in, float* __restrict__ out,
                            const unsigned* __restrict__ scalebits,
                            const float* __restrict__ bias)
{
    extern __shared__ float4 dsm4[];
    __shared__ float red[32];
    fwht_dim0_body<false, true>(in, out, dsm4, red, FD, blockIdx.x * 8,
                                1.0f / 4096.0f, scalebits, nullptr, bias);
}

// ===========================================================================
// Stochastic quantization (merged x + w kernel; also resets GEMM tile counter)
// ===========================================================================
__device__ __forceinline__ int squant1(float xv, float nv, float s) {
    float xs = xv / s;
    float f  = floorf(xs);
    float qv = f + ((nv < xs - f) ? 1.0f : 0.0f);
    qv = fminf(fmaxf(qv, -127.0f), 127.0f);
    return (int)qv;
}

#define QX_BLOCKS 1024

__global__ __launch_bounds__(256)
void quant_xw_kernel(const float* __restrict__ xr, const float* __restrict__ nx,
                     signed char* __restrict__ qx,
                     const float* __restrict__ wr, const float* __restrict__ nw,
                     signed char* __restrict__ qwT,
                     const unsigned* __restrict__ mx)
{
    const int tid = threadIdx.x;
    if (blockIdx.x == 0 && tid == 0) g_tilectr = 0u;   // stream-ordered before GEMM

    if (blockIdx.x < QX_BLOCKS) {
        const float s = __uint_as_float(mx[0]) / 127.0f;
        const float4* v = (const float4*)xr;
        const float4* nz4 = (const float4*)nx;
        char4* q = (char4*)qx;
        const int n4 = (int)((size_t)BD * ID / 4);
        for (int i = blockIdx.x * 256 + tid; i < n4; i += QX_BLOCKS * 256) {
            float4 xv = v[i], nv = nz4[i];
            q[i] = make_char4((signed char)squant1(xv.x, nv.x, s),
                              (signed char)squant1(xv.y, nv.y, s),
                              (signed char)squant1(xv.z, nv.z, s),
                              (signed char)squant1(xv.w, nv.w, s));
        }
    } else {
        __shared__ signed char tb[64][68];
        const float s = __uint_as_float(mx[1]) / 127.0f;
        const int bx = blockIdx.x - QX_BLOCKS;
        const int k0 = (bx & 31) * 64;
        const int n0 = (bx >> 5) * 64;

        #pragma unroll
        for (int it = 0; it < 4; ++it) {
            int idx = tid + it * 256;
            int kl = idx >> 4, nq = (idx & 15) * 4;
            size_t gi = (size_t)(k0 + kl) * FD + n0 + nq;
            float4 xv = *(const float4*)(wr + gi);
            float4 nv = *(const float4*)(nw + gi);
            tb[nq + 0][kl] = (signed char)squant1(xv.x, nv.x, s);
            tb[nq + 1][kl] = (signed char)squant1(xv.y, nv.y, s);
            tb[nq + 2][kl] = (signed char)squant1(xv.z, nv.z, s);
            tb[nq + 3][kl] = (signed char)squant1(xv.w, nv.w, s);
        }
        __syncthreads();

        #pragma unroll
        for (int it = 0; it < 4; ++it) {
            int idx = tid + it * 256;
            int nl = idx >> 4, k4 = (idx & 15) * 4;
            char4 vv = make_char4(tb[nl][k4], tb[nl][k4 + 1], tb[nl][k4 + 2], tb[nl][k4 + 3]);
            *(char4*)&qwT[(size_t)(n0 + nl) * ID + k0 + k4] = vv;
        }
    }
}

// ===========================================================================
// Hybrid persistent int8 GEMM with work stealing.
//   tile = 128x128, K-step = 128 bytes (16 iterations), 3-stage cp.async ring
//   pitch 144 (128B data + 16B pad -> conflict-free)
//   warps 0-7 (mma): 16 rows x cols [0,72) each (9 chunks), via ldmatrix
//   warps 8-11 (dp4a): cols [72,128); each thread 4 rows x 14 cols
// ===========================================================================
#define GM_PITCH  144
#define GM_STAGES 3
#define GM_STAGE_BYTES (256 * GM_PITCH)          // 36864
#define GM_SMEM   (GM_STAGES * GM_STAGE_BYTES)   // 110592
#define GM_NKT    (ID / 128)                     // 16
#define GM_NTILES ((BD / 128) * (FD / 128))      // 1024
#define GM_GRID   304
#define GM_NMMA   9                              // 8-col chunks per mma warp
#define GM_DPC    14                             // dp4a cols per thread
#define GM_DPBASE 72                             // first dp4a column

__device__ __forceinline__ void cp16(unsigned smem, const void* gmem) {
    asm volatile("cp.async.cg.shared.global [%0], [%1], 16;" :: "r"(smem), "l"(gmem));
}

__global__ __launch_bounds__(384, 2)
void gemm_s8_kernel(const signed char* __restrict__ A,
                    const signed char* __restrict__ B,
                    int* __restrict__ C)
{
    extern __shared__ __align__(16) signed char sm[];
    __shared__ unsigned s_tile;

    const int tid  = threadIdx.x;
    const int lane = tid & 31;
    const int warp = tid >> 5;
    const unsigned smbase = (unsigned)__cvta_generic_to_shared(sm);

    // ldmatrix per-lane offsets within a stage
    const unsigned a_lane_off =
        (unsigned)((warp * 16 + (lane & 15)) * GM_PITCH + (lane >> 4) * 16);
    const unsigned b_lane_off =
        (unsigned)(128 * GM_PITCH + (lane & 7) * GM_PITCH + ((lane >> 3) & 1) * 16);

    while (true) {
        __syncthreads();                    // all old-tile smem reads done
        if (tid == 0) s_tile = atomicAdd(&g_tilectr, 1u);
        __syncthreads();
        const unsigned t = s_tile;
        if (t >= GM_NTILES) return;

        const int m0 = (int)(t >> 5) * 128;
        const int n0 = (int)(t & 31) * 128;

        // stage loader: 256 rows (A 0-127, B 128-255) x 128B, 8 cp16/thread
        auto load_stage = [&](int kt, int st) {
            if (tid < 256) {
                const unsigned sbase = smbase + st * GM_STAGE_BYTES;
                const signed char* ga = A + (size_t)m0 * ID + kt * 128;
                const signed char* gb = B + (size_t)n0 * ID + kt * 128;
                #pragma unroll
                for (int i = 0; i < 4; ++i) {          // A
                    int idx = tid + i * 256;
                    int row = idx >> 3, kb = idx & 7;
                    cp16(sbase + row * GM_PITCH + kb * 16,
                         ga + (size_t)row * ID + kb * 16);
                }
                #pragma unroll
                for (int i = 0; i < 4; ++i) {          // B
                    int idx = tid + i * 256;
                    int row = idx >> 3, kb = idx & 7;
                    cp16(sbase + (128 + row) * GM_PITCH + kb * 16,
                         gb + (size_t)row * ID + kb * 16);
                }
            }
            asm volatile("cp.async.commit_group;");
        };

        load_stage(0, 0);
        load_stage(1, 1);

        int st_cur = 0;       // kt % 3
        int st_nxt = 2;       // (kt+2) % 3

        if (warp < 8) {
            // ---- mma warps: rows [16*warp, 16*warp+16), cols [0,72) ----
            int c[GM_NMMA][4];
            #pragma unroll
            for (int j = 0; j < GM_NMMA; ++j)
                #pragma unroll
                for (int k = 0; k < 4; ++k) c[j][k] = 0;

            for (int kt = 0; kt < GM_NKT; ++kt) {
                if (kt < GM_NKT - 1) asm volatile("cp.async.wait_group 1;");
                else                 asm volatile("cp.async.wait_group 0;");
                __syncthreads();

                if (kt + 2 < GM_NKT) load_stage(kt + 2, st_nxt);

                const unsigned stage = smbase + st_cur * GM_STAGE_BYTES;
                const unsigned aaddr = stage + a_lane_off;
                const unsigned baddr = stage + b_lane_off;

                #pragma unroll
                for (int h = 0; h < 4; ++h) {
                    int a0, a1, a2, a3;
                    asm volatile(
                        "ldmatrix.sync.aligned.m8n8.x4.shared.b16 {%0,%1,%2,%3}, [%4];"
                        : "=r"(a0), "=r"(a1), "=r"(a2), "=r"(a3)
                        : "r"(aaddr + h * 32));
                    #pragma unroll
                    for (int ni = 0; ni < GM_NMMA; ++ni) {
                        int b0, b1;
                        asm volatile(
                            "ldmatrix.sync.aligned.m8n8.x2.shared.b16 {%0,%1}, [%2];"
                            : "=r"(b0), "=r"(b1)
                            : "r"(baddr + ni * (8 * GM_PITCH) + h * 32));
                        asm volatile(
                            "mma.sync.aligned.m16n8k32.row.col.s32.s8.s8.s32 "
                            "{%0,%1,%2,%3},{%4,%5,%6,%7},{%8,%9},{%0,%1,%2,%3};"
                            : "+r"(c[ni][0]), "+r"(c[ni][1]),
                              "+r"(c[ni][2]), "+r"(c[ni][3])
                            : "r"(a0), "r"(a1), "r"(a2), "r"(a3),
                              "r"(b0), "r"(b1));
                    }
                }
                st_cur = (st_cur == 2) ? 0 : st_cur + 1;
                st_nxt = (st_nxt == 2) ? 0 : st_nxt + 1;
            }

            {
                int row = m0 + warp * 16 + (lane >> 2);
                #pragma unroll
                for (int ni = 0; ni < GM_NMMA; ++ni) {
                    int col = n0 + ni * 8 + (lane & 3) * 2;
                    *(int2*)&C[(size_t)row * FD + col]       = make_int2(c[ni][0], c[ni][1]);
                    *(int2*)&C[(size_t)(row + 8) * FD + col] = make_int2(c[ni][2], c[ni][3]);
                }
            }
        } else {
            // ---- dp4a warps: cols [72,128); thread: 4 rows x 14 cols ----
            const int d  = tid - 256;      // 0..127
            const int cg = d & 3;
            const int rg = d >> 2;         // 0..31

            int acc[4][GM_DPC];
            #pragma unroll
            for (int i = 0; i < 4; ++i)
                #pragma unroll
                for (int k = 0; k < GM_DPC; ++k) acc[i][k] = 0;

            for (int kt = 0; kt < GM_NKT; ++kt) {
                if (kt < GM_NKT - 1) asm volatile("cp.async.wait_group 1;");
                else                 asm volatile("cp.async.wait_group 0;");
                __syncthreads();

                if (kt + 2 < GM_NKT) load_stage(kt + 2, st_nxt);

                const signed char* as = sm + st_cur * GM_STAGE_BYTES;
                const signed char* bs = as + 128 * GM_PITCH;

                #pragma unroll
                for (int ch = 0; ch < 8; ++ch) {
                    int4 a4[4];
                    #pragma unroll
                    for (int i = 0; i < 4; ++i)
                        a4[i] = *(const int4*)(as + (rg + 32 * i) * GM_PITCH + ch * 16);
                    #pragma unroll
                    for (int k = 0; k < GM_DPC; ++k) {
                        int4 b4 = *(const int4*)(bs + (GM_DPBASE + cg + 4 * k) * GM_PITCH + ch * 16);
                        #pragma unroll
                        for (int i = 0; i < 4; ++i) {
                            int s = acc[i][k];
                            s = __dp4a(a4[i].x, b4.x, s);
                            s = __dp4a(a4[i].y, b4.y, s);
                            s = __dp4a(a4[i].z, b4.z, s);
                            s = __dp4a(a4[i].w, b4.w, s);
                            acc[i][k] = s;
                        }
                    }
                }
                st_cur = (st_cur == 2) ? 0 : st_cur + 1;
                st_nxt = (st_nxt == 2) ? 0 : st_nxt + 1;
            }

            #pragma unroll
            for (int i = 0; i < 4; ++i) {
                int* cp = C + (size_t)(m0 + rg + 32 * i) * FD + n0 + GM_DPBASE + cg;
                #pragma unroll
                for (int k = 0; k < GM_DPC; ++k) cp[4 * k] = acc[i][k];
            }
        }
    }
}

// ---------------------------------------------------------------------------
extern "C" void kernel_launch(void* const* d_in, const int* in_sizes, int n_in,
                              void* d_out, int out_size)
{
    const float* x    = (const float*)d_in[0];  // [4096, 2048]
    const float* w    = (const float*)d_in[1];  // [2048, 4096]
    const float* bias = (const float*)d_in[2];  // [4096]
    const float* nx   = (const float*)d_in[5];  // [4096, 2048]
    const float* nw   = (const float*)d_in[6];  // [2048, 4096]
    float* out = (float*)d_out;                 // [4096, 4096]

    float *xbuf, *wbuf, *zbuf;
    int* acc;
    signed char *qx, *qwT;
    unsigned* mx;
    cudaGetSymbolAddress((void**)&xbuf, g_xbuf);
    cudaGetSymbolAddress((void**)&wbuf, g_wbuf);
    cudaGetSymbolAddress((void**)&zbuf, g_zbuf);
    cudaGetSymbolAddress((void**)&acc,  g_acc);
    cudaGetSymbolAddress((void**)&qx,   g_qx);
    cudaGetSymbolAddress((void**)&qwT,  g_qwT);
    cudaGetSymbolAddress((void**)&mx,   g_maxbits);

    const int SMEM_D0 = 8 * 1024 * sizeof(float4);  // 128 KB
    cudaFuncSetAttribute(fwht_dim0_x_kernel,
                         cudaFuncAttributeMaxDynamicSharedMemorySize, SMEM_D0);
    cudaFuncSetAttribute(fwht_dim0_final_kernel,
                         cudaFuncAttributeMaxDynamicSharedMemorySize, SMEM_D0);
    cudaFuncSetAttribute(gemm_s8_kernel,
                         cudaFuncAttributeMaxDynamicSharedMemorySize, GM_SMEM);

    // [idx 2] xr = FWHT_batch(x)/64 ; max -> mx[0]
    fwht_dim0_x_kernel<<<ID / 8, 1024, SMEM_D0>>>(x, xbuf, mx);

    // [idx 3] wr = FWHT_feat(w)/64 ; max -> mx[1]
    fwht_rows_w_kernel<<<ID, 1024>>>(w, wbuf, mx);

    // [idx 4] stochastic int8 quantization (also resets g_tilectr)
    quant_xw_kernel<<<QX_BLOCKS + 2048, 256>>>(xbuf, nx, qx, wbuf, nw, qwT, mx);

    // [idx 5] persistent hybrid int8 GEMM (mma cols 0-71 + dp4a cols 72-127)
    gemm_s8_kernel<<<GM_GRID, 384, GM_SMEM>>>(qx, qwT, acc);

    // [idx 6] y1 = FWHT_feat(acc)
    fwht_rows_acc_kernel<<<BD, 1024>>>(acc, zbuf);

    // [idx 7] y = FWHT_batch(y1) * sx*sw/4096 + bias
    fwht_dim0_final_kernel<<<FD / 8, 1024, SMEM_D0>>>(zbuf, out, mx, bias);
}

// round 13
// speedup vs baseline: 1.0423x; 1.0423x over previous
#include <cuda_runtime.h>
#include <cstdint>
#include <cstddef>

#define BD 4096   // batch (M)
#define ID 2048   // in features (K)
#define FD 4096   // out features (N)

// ---------------------------------------------------------------------------
// Scratch (device globals; zero-initialized at load; no dynamic allocation)
// ---------------------------------------------------------------------------
__device__ float       g_xbuf[(size_t)BD * ID];
__device__ float       g_wbuf[(size_t)ID * FD];
__device__ float       g_zbuf[(size_t)BD * FD];
__device__ int         g_acc [(size_t)BD * FD];
__device__ signed char g_qx  [(size_t)BD * ID];
__device__ signed char g_qwT [(size_t)FD * ID];
// atomicMax over identical inputs is idempotent -> deterministic across replays
__device__ unsigned    g_maxbits[2];
// GEMM work-stealing counter; reset by quant_xw_kernel block 0 each run
__device__ unsigned    g_tilectr;

// ===========================================================================
// FWHT building blocks
// ===========================================================================
template<typename Tin, bool DO_MAX>
__device__ __forceinline__ void fwht_row_body(const Tin* __restrict__ in,
                                              float* __restrict__ out,
                                              float4* s4, float* red,
                                              int row, float scale,
                                              unsigned* __restrict__ maxbits)
{
    const int t = threadIdx.x;
    const int l = t & 31;
    const int w = t >> 5;

    float v[4];
    {
        const Tin* rp = in + (size_t)row * 4096;
        float4 f;
        if constexpr ((bool)__is_same(Tin, int)) {
            int4 q = ((const int4*)rp)[t];
            f = make_float4((float)q.x, (float)q.y, (float)q.z, (float)q.w);
        } else {
            f = ((const float4*)rp)[t];
        }
        v[0] = f.x; v[1] = f.y; v[2] = f.z; v[3] = f.w;
    }

    { float a, b;
      a = v[0]; b = v[1]; v[0] = a + b; v[1] = a - b;
      a = v[2]; b = v[3]; v[2] = a + b; v[3] = a - b;
      a = v[0]; b = v[2]; v[0] = a + b; v[2] = a - b;
      a = v[1]; b = v[3]; v[1] = a + b; v[3] = a - b; }

    #pragma unroll
    for (int m = 1; m <= 16; m <<= 1) {
        #pragma unroll
        for (int j = 0; j < 4; ++j) {
            float per = __shfl_xor_sync(0xffffffffu, v[j], m);
            v[j] = (l & m) ? per - v[j] : v[j] + per;
        }
    }

    s4[t ^ w] = make_float4(v[0], v[1], v[2], v[3]);
    __syncthreads();
    {
        int r4 = (l << 5) | w;
        float4 f = s4[r4 ^ l];
        v[0] = f.x; v[1] = f.y; v[2] = f.z; v[3] = f.w;
    }

    #pragma unroll
    for (int m = 1; m <= 16; m <<= 1) {
        #pragma unroll
        for (int j = 0; j < 4; ++j) {
            float per = __shfl_xor_sync(0xffffffffu, v[j], m);
            v[j] = (l & m) ? per - v[j] : v[j] + per;
        }
    }

    {
        int r4 = (l << 5) | w;
        s4[r4 ^ l] = make_float4(v[0], v[1], v[2], v[3]);
    }
    __syncthreads();
    float4 f = s4[t ^ w];

    float4 o = make_float4(f.x * scale, f.y * scale, f.z * scale, f.w * scale);
    ((float4*)(out + (size_t)row * 4096))[t] = o;

    if (DO_MAX) {
        float lmax = fmaxf(fmaxf(fabsf(o.x), fabsf(o.y)), fmaxf(fabsf(o.z), fabsf(o.w)));
        #pragma unroll
        for (int m = 16; m; m >>= 1) lmax = fmaxf(lmax, __shfl_xor_sync(0xffffffffu, lmax, m));
        if (l == 0) red[w] = lmax;
        __syncthreads();
        if (t < 32) {
            float r2 = red[t];
            #pragma unroll
            for (int m = 16; m; m >>= 1) r2 = fmaxf(r2, __shfl_xor_sync(0xffffffffu, r2, m));
            if (t == 0) atomicMax(maxbits, __float_as_uint(r2));
        }
    }
}

template<bool DO_MAX, bool FINAL>
__device__ __forceinline__ void fwht_dim0_body(const float* __restrict__ in,
                                               float* __restrict__ out,
                                               float4* sm4, float* red,
                                               int ncols, int c0, float scale,
                                               const unsigned* __restrict__ scalebits,
                                               unsigned* __restrict__ maxbits,
                                               const float* __restrict__ bias)
{
    const int t = threadIdx.x;
    const int c = t & 7;
    const int p = t >> 3;
    const int l = t & 31;
    const int w = t >> 5;

    float v[32];

    {
        const float* ip = in + (size_t)(p << 5) * ncols + c0 + c;
        #pragma unroll
        for (int j = 0; j < 32; ++j) v[j] = ip[(size_t)j * ncols];
    }

    #pragma unroll
    for (int st = 0; st < 5; ++st) {
        const int h = 1 << st;
        #pragma unroll
        for (int j = 0; j < 32; ++j)
            if ((j & h) == 0) {
                float a = v[j], b = v[j + h];
                v[j] = a + b; v[j + h] = a - b;
            }
    }

    #pragma unroll
    for (int m = 8; m <= 16; m <<= 1) {
        #pragma unroll
        for (int j = 0; j < 32; ++j) {
            float per = __shfl_xor_sync(0xffffffffu, v[j], m);
            v[j] = (l & m) ? per - v[j] : v[j] + per;
        }
    }

    #pragma unroll
    for (int jj = 0; jj < 8; ++jj) {
        int phys = (c << 10) + (((p << 3) + jj) ^ c);
        sm4[phys] = make_float4(v[4 * jj], v[4 * jj + 1], v[4 * jj + 2], v[4 * jj + 3]);
    }
    __syncthreads();

    {
        const float* smf = (const float*)sm4;
        #pragma unroll
        for (int j = 0; j < 32; ++j) {
            int q  = (j << 5) + w;
            int phys = (c << 10) + (q ^ c);
            v[j] = smf[phys * 4 + (p & 3)];
        }
    }

    #pragma unroll
    for (int st = 0; st < 5; ++st) {
        const int h = 1 << st;
        #pragma unroll
        for (int j = 0; j < 32; ++j)
            if ((j & h) == 0) {
                float a = v[j], b = v[j + h];
                v[j] = a + b; v[j + h] = a - b;
            }
    }

    float sc = scale;
    float bv = 0.0f;
    if (FINAL) {
        float sx = __uint_as_float(scalebits[0]) / 127.0f;
        float sw = __uint_as_float(scalebits[1]) / 127.0f;
        sc *= sx * sw;
        bv = bias[c0 + c];
    }

    float lmax = 0.0f;
    {
        float* op = out + (size_t)p * ncols + c0 + c;
        #pragma unroll
        for (int j = 0; j < 32; ++j) {
            float o = v[j] * sc + bv;
            op[(size_t)(j << 7) * ncols] = o;
            if (DO_MAX) lmax = fmaxf(lmax, fabsf(o));
        }
    }

    if (DO_MAX) {
        #pragma unroll
        for (int m = 16; m; m >>= 1) lmax = fmaxf(lmax, __shfl_xor_sync(0xffffffffu, lmax, m));
        if (l == 0) red[w] = lmax;
        __syncthreads();
        if (t < 32) {
            float r2 = red[t];
            #pragma unroll
            for (int m = 16; m; m >>= 1) r2 = fmaxf(r2, __shfl_xor_sync(0xffffffffu, r2, m));
            if (t == 0) atomicMax(maxbits, __float_as_uint(r2));
        }
    }
}

__global__ __launch_bounds__(1024)
void fwht_dim0_x_kernel(const float* __restrict__ x, float* __restrict__ xr,
                        unsigned* __restrict__ mx)
{
    extern __shared__ float4 dsm4[];
    __shared__ float red[32];
    fwht_dim0_body<true, false>(x, xr, dsm4, red, ID, blockIdx.x * 8,
                                1.0f / 64.0f, nullptr, mx + 0, nullptr);
}

__global__ __launch_bounds__(1024, 2)
void fwht_rows_w_kernel(const float* __restrict__ w, float* __restrict__ wr,
                        unsigned* __restrict__ mx)
{
    __shared__ float4 s4[1024];
    __shared__ float red[32];
    fwht_row_body<float, true>(w, wr, s4, red, blockIdx.x, 1.0f / 64.0f, mx + 1);
}

__global__ __launch_bounds__(1024, 2)
void fwht_rows_acc_kernel(const int* __restrict__ in, float* __restrict__ out)
{
    __shared__ float4 s4[1024];
    __shared__ float red[32];
    fwht_row_body<int, false>(in, out, s4, red, blockIdx.x, 1.0f, nullptr);
}

__global__ __launch_bounds__(1024)
void fwht_dim0_final_kernel(const float* __restrict__ in, float* __restrict__ out,
                            const unsigned* __restrict__ scalebits,
                            const float* __restrict__ bias)
{
    extern __shared__ float4 dsm4[];
    __shared__ float red[32];
    fwht_dim0_body<false, true>(in, out, dsm4, red, FD, blockIdx.x * 8,
                                1.0f / 4096.0f, scalebits, nullptr, bias);
}

// ===========================================================================
// Stochastic quantization (merged x + w kernel; also resets GEMM tile counter)
// ===========================================================================
__device__ __forceinline__ int squant1(float xv, float nv, float s) {
    float xs = xv / s;
    float f  = floorf(xs);
    float qv = f + ((nv < xs - f) ? 1.0f : 0.0f);
    qv = fminf(fmaxf(qv, -127.0f), 127.0f);
    return (int)qv;
}

#define QX_BLOCKS 1024

__global__ __launch_bounds__(256)
void quant_xw_kernel(const float* __restrict__ xr, const float* __restrict__ nx,
                     signed char* __restrict__ qx,
                     const float* __restrict__ wr, const float* __restrict__ nw,
                     signed char* __restrict__ qwT,
                     const unsigned* __restrict__ mx)
{
    const int tid = threadIdx.x;
    if (blockIdx.x == 0 && tid == 0) g_tilectr = 0u;   // stream-ordered before GEMM

    if (blockIdx.x < QX_BLOCKS) {
        const float s = __uint_as_float(mx[0]) / 127.0f;
        const float4* v = (const float4*)xr;
        const float4* nz4 = (const float4*)nx;
        char4* q = (char4*)qx;
        const int n4 = (int)((size_t)BD * ID / 4);
        for (int i = blockIdx.x * 256 + tid; i < n4; i += QX_BLOCKS * 256) {
            float4 xv = v[i], nv = nz4[i];
            q[i] = make_char4((signed char)squant1(xv.x, nv.x, s),
                              (signed char)squant1(xv.y, nv.y, s),
                              (signed char)squant1(xv.z, nv.z, s),
                              (signed char)squant1(xv.w, nv.w, s));
        }
    } else {
        __shared__ signed char tb[64][68];
        const float s = __uint_as_float(mx[1]) / 127.0f;
        const int bx = blockIdx.x - QX_BLOCKS;
        const int k0 = (bx & 31) * 64;
        const int n0 = (bx >> 5) * 64;

        #pragma unroll
        for (int it = 0; it < 4; ++it) {
            int idx = tid + it * 256;
            int kl = idx >> 4, nq = (idx & 15) * 4;
            size_t gi = (size_t)(k0 + kl) * FD + n0 + nq;
            float4 xv = *(const float4*)(wr + gi);
            float4 nv = *(const float4*)(nw + gi);
            tb[nq + 0][kl] = (signed char)squant1(xv.x, nv.x, s);
            tb[nq + 1][kl] = (signed char)squant1(xv.y, nv.y, s);
            tb[nq + 2][kl] = (signed char)squant1(xv.z, nv.z, s);
            tb[nq + 3][kl] = (signed char)squant1(xv.w, nv.w, s);
        }
        __syncthreads();

        #pragma unroll
        for (int it = 0; it < 4; ++it) {
            int idx = tid + it * 256;
            int nl = idx >> 4, k4 = (idx & 15) * 4;
            char4 vv = make_char4(tb[nl][k4], tb[nl][k4 + 1], tb[nl][k4 + 2], tb[nl][k4 + 3]);
            *(char4*)&qwT[(size_t)(n0 + nl) * ID + k0 + k4] = vv;
        }
    }
}

// ===========================================================================
// Hybrid persistent int8 GEMM, warp-specialized with named-barrier pipeline.
//   tile = 128x128, K-step = 128 bytes (16 iters), 3-stage cp.async ring
//   warps 0-7 (mma+loader): 16 rows x cols [0,80), ldmatrix fragments
//   warps 8-11 (dp4a): cols [80,128); 4 rows x 12 cols per thread
//   BAR_READY (4): mma arrive after wait_group -> dp4a sync (stage loaded)
//   BAR_FREE  (5): dp4a arrive after consuming  -> mma sync (stage reusable)
// ===========================================================================
#define GM_PITCH  144
#define GM_STAGES 3
#define GM_STAGE_BYTES (256 * GM_PITCH)          // 36864
#define GM_SMEM   (GM_STAGES * GM_STAGE_BYTES)   // 110592
#define GM_NKT    (ID / 128)                     // 16
#define GM_NTILES ((BD / 128) * (FD / 128))      // 1024
#define GM_GRID   304
#define GM_NMMA   10                             // 8-col chunks per mma warp
#define GM_DPC    12                             // dp4a cols per thread
#define GM_DPBASE 80                             // first dp4a column

#define BAR_READY 4
#define BAR_FREE  5
#define BAR_CNT   384

__device__ __forceinline__ void cp16(unsigned smem, const void* gmem) {
    asm volatile("cp.async.cg.shared.global [%0], [%1], 16;" :: "r"(smem), "l"(gmem));
}
__device__ __forceinline__ void bar_arrive(int b) {
    asm volatile("bar.arrive %0, %1;" :: "r"(b), "r"(BAR_CNT) : "memory");
}
__device__ __forceinline__ void bar_wait(int b) {
    asm volatile("bar.sync %0, %1;" :: "r"(b), "r"(BAR_CNT) : "memory");
}

__global__ __launch_bounds__(384, 2)
void gemm_s8_kernel(const signed char* __restrict__ A,
                    const signed char* __restrict__ B,
                    int* __restrict__ C)
{
    extern __shared__ __align__(16) signed char sm[];
    __shared__ unsigned s_tile;

    const int tid  = threadIdx.x;
    const int lane = tid & 31;
    const int warp = tid >> 5;
    const unsigned smbase = (unsigned)__cvta_generic_to_shared(sm);

    // ldmatrix per-lane offsets within a stage
    const unsigned a_lane_off =
        (unsigned)((warp * 16 + (lane & 15)) * GM_PITCH + (lane >> 4) * 16);
    const unsigned b_lane_off =
        (unsigned)(128 * GM_PITCH + (lane & 7) * GM_PITCH + ((lane >> 3) & 1) * 16);

    while (true) {
        __syncthreads();                    // all old-tile smem reads done
        if (tid == 0) s_tile = atomicAdd(&g_tilectr, 1u);
        __syncthreads();
        const unsigned t = s_tile;
        if (t >= GM_NTILES) return;

        const int m0 = (int)(t >> 5) * 128;
        const int n0 = (int)(t & 31) * 128;

        if (warp < 8) {
            // ======== producer + mma consumer warps ========
            auto load_stage = [&](int kt, int st) {
                const unsigned sbase = smbase + st * GM_STAGE_BYTES;
                const signed char* ga = A + (size_t)m0 * ID + kt * 128;
                const signed char* gb = B + (size_t)n0 * ID + kt * 128;
                #pragma unroll
                for (int i = 0; i < 4; ++i) {          // A
                    int idx = tid + i * 256;
                    int row = idx >> 3, kb = idx & 7;
                    cp16(sbase + row * GM_PITCH + kb * 16,
                         ga + (size_t)row * ID + kb * 16);
                }
                #pragma unroll
                for (int i = 0; i < 4; ++i) {          // B
                    int idx = tid + i * 256;
                    int row = idx >> 3, kb = idx & 7;
                    cp16(sbase + (128 + row) * GM_PITCH + kb * 16,
                         gb + (size_t)row * ID + kb * 16);
                }
                asm volatile("cp.async.commit_group;");
            };

            load_stage(0, 0);
            load_stage(1, 1);

            int st_cur = 0;       // kt % 3
            int st_nxt = 2;       // (kt+2) % 3

            int c[GM_NMMA][4];
            #pragma unroll
            for (int j = 0; j < GM_NMMA; ++j)
                #pragma unroll
                for (int k = 0; k < 4; ++k) c[j][k] = 0;

            for (int kt = 0; kt < GM_NKT; ++kt) {
                if (kt < GM_NKT - 1) asm volatile("cp.async.wait_group 1;" ::: "memory");
                else                 asm volatile("cp.async.wait_group 0;" ::: "memory");
                bar_arrive(BAR_READY);           // stage kt loaded -> dp4a
                bar_wait(BAR_FREE);              // stage (kt+2)%3 free to overwrite

                if (kt + 2 < GM_NKT) load_stage(kt + 2, st_nxt);

                const unsigned stage = smbase + st_cur * GM_STAGE_BYTES;
                const unsigned aaddr = stage + a_lane_off;
                const unsigned baddr = stage + b_lane_off;

                #pragma unroll
                for (int h = 0; h < 4; ++h) {
                    int a0, a1, a2, a3;
                    asm volatile(
                        "ldmatrix.sync.aligned.m8n8.x4.shared.b16 {%0,%1,%2,%3}, [%4];"
                        : "=r"(a0), "=r"(a1), "=r"(a2), "=r"(a3)
                        : "r"(aaddr + h * 32));
                    #pragma unroll
                    for (int ni = 0; ni < GM_NMMA; ++ni) {
                        int b0, b1;
                        asm volatile(
                            "ldmatrix.sync.aligned.m8n8.x2.shared.b16 {%0,%1}, [%2];"
                            : "=r"(b0), "=r"(b1)
                            : "r"(baddr + ni * (8 * GM_PITCH) + h * 32));
                        asm volatile(
                            "mma.sync.aligned.m16n8k32.row.col.s32.s8.s8.s32 "
                            "{%0,%1,%2,%3},{%4,%5,%6,%7},{%8,%9},{%0,%1,%2,%3};"
                            : "+r"(c[ni][0]), "+r"(c[ni][1]),
                              "+r"(c[ni][2]), "+r"(c[ni][3])
                            : "r"(a0), "r"(a1), "r"(a2), "r"(a3),
                              "r"(b0), "r"(b1));
                    }
                }
                st_cur = (st_cur == 2) ? 0 : st_cur + 1;
                st_nxt = (st_nxt == 2) ? 0 : st_nxt + 1;
            }

            {
                int row = m0 + warp * 16 + (lane >> 2);
                #pragma unroll
                for (int ni = 0; ni < GM_NMMA; ++ni) {
                    int col = n0 + ni * 8 + (lane & 3) * 2;
                    *(int2*)&C[(size_t)row * FD + col]       = make_int2(c[ni][0], c[ni][1]);
                    *(int2*)&C[(size_t)(row + 8) * FD + col] = make_int2(c[ni][2], c[ni][3]);
                }
            }
        } else {
            // ======== dp4a consumer warps: cols [80,128) ========
            const int d  = tid - 256;      // 0..127
            const int cg = d & 3;
            const int rg = d >> 2;         // 0..31

            bar_arrive(BAR_FREE);          // pre-arm: stage 2 considered free

            int acc[4][GM_DPC];
            #pragma unroll
            for (int i = 0; i < 4; ++i)
                #pragma unroll
                for (int k = 0; k < GM_DPC; ++k) acc[i][k] = 0;

            int st_cur = 0;
            for (int kt = 0; kt < GM_NKT; ++kt) {
                bar_wait(BAR_READY);       // stage kt loaded

                const signed char* as = sm + st_cur * GM_STAGE_BYTES;
                const signed char* bs = as + 128 * GM_PITCH;

                #pragma unroll
                for (int ch = 0; ch < 8; ++ch) {
                    int4 a4[4];
                    #pragma unroll
                    for (int i = 0; i < 4; ++i)
                        a4[i] = *(const int4*)(as + (rg + 32 * i) * GM_PITCH + ch * 16);
                    #pragma unroll
                    for (int k = 0; k < GM_DPC; ++k) {
                        int4 b4 = *(const int4*)(bs + (GM_DPBASE + cg + 4 * k) * GM_PITCH + ch * 16);
                        #pragma unroll
                        for (int i = 0; i < 4; ++i) {
                            int s = acc[i][k];
                            s = __dp4a(a4[i].x, b4.x, s);
                            s = __dp4a(a4[i].y, b4.y, s);
                            s = __dp4a(a4[i].z, b4.z, s);
                            s = __dp4a(a4[i].w, b4.w, s);
                            acc[i][k] = s;
                        }
                    }
                }

                if (kt < GM_NKT - 1) bar_arrive(BAR_FREE);   // stage kt consumed
                st_cur = (st_cur == 2) ? 0 : st_cur + 1;
            }

            #pragma unroll
            for (int i = 0; i < 4; ++i) {
                int* cp = C + (size_t)(m0 + rg + 32 * i) * FD + n0 + GM_DPBASE + cg;
                #pragma unroll
                for (int k = 0; k < GM_DPC; ++k) cp[4 * k] = acc[i][k];
            }
        }
    }
}

// ---------------------------------------------------------------------------
extern "C" void kernel_launch(void* const* d_in, const int* in_sizes, int n_in,
                              void* d_out, int out_size)
{
    const float* x    = (const float*)d_in[0];  // [4096, 2048]
    const float* w    = (const float*)d_in[1];  // [2048, 4096]
    const float* bias = (const float*)d_in[2];  // [4096]
    const float* nx   = (const float*)d_in[5];  // [4096, 2048]
    const float* nw   = (const float*)d_in[6];  // [2048, 4096]
    float* out = (float*)d_out;                 // [4096, 4096]

    float *xbuf, *wbuf, *zbuf;
    int* acc;
    signed char *qx, *qwT;
    unsigned* mx;
    cudaGetSymbolAddress((void**)&xbuf, g_xbuf);
    cudaGetSymbolAddress((void**)&wbuf, g_wbuf);
    cudaGetSymbolAddress((void**)&zbuf, g_zbuf);
    cudaGetSymbolAddress((void**)&acc,  g_acc);
    cudaGetSymbolAddress((void**)&qx,   g_qx);
    cudaGetSymbolAddress((void**)&qwT,  g_qwT);
    cudaGetSymbolAddress((void**)&mx,   g_maxbits);

    const int SMEM_D0 = 8 * 1024 * sizeof(float4);  // 128 KB
    cudaFuncSetAttribute(fwht_dim0_x_kernel,
                         cudaFuncAttributeMaxDynamicSharedMemorySize, SMEM_D0);
    cudaFuncSetAttribute(fwht_dim0_final_kernel,
                         cudaFuncAttributeMaxDynamicSharedMemorySize, SMEM_D0);
    cudaFuncSetAttribute(gemm_s8_kernel,
                         cudaFuncAttributeMaxDynamicSharedMemorySize, GM_SMEM);

    // [idx 2] xr = FWHT_batch(x)/64 ; max -> mx[0]
    fwht_dim0_x_kernel<<<ID / 8, 1024, SMEM_D0>>>(x, xbuf, mx);

    // [idx 3] wr = FWHT_feat(w)/64 ; max -> mx[1]
    fwht_rows_w_kernel<<<ID, 1024>>>(w, wbuf, mx);

    // [idx 4] stochastic int8 quantization (also resets g_tilectr)
    quant_xw_kernel<<<QX_BLOCKS + 2048, 256>>>(xbuf, nx, qx, wbuf, nw, qwT, mx);

    // [idx 5] persistent warp-specialized hybrid int8 GEMM (mma 0-79 + dp4a 80-127)
    gemm_s8_kernel<<<GM_GRID, 384, GM_SMEM>>>(qx, qwT, acc);

    // [idx 6] y1 = FWHT_feat(acc)
    fwht_rows_acc_kernel<<<BD, 1024>>>(acc, zbuf);

    // [idx 7] y = FWHT_batch(y1) * sx*sw/4096 + bias
    fwht_dim0_final_kernel<<<FD / 8, 1024, SMEM_D0>>>(zbuf, out, mx, bias);
}